// round 16
// baseline (speedup 1.0000x reference)
#include <cuda_runtime.h>
#include <cuda_bf16.h>
#include <limits.h>

#define H_HALF 4096
#define BLOCK 256
#define NWARP (BLOCK / 32)
#define V4 4                 // 4 float4 per thread = 16 floats; 256*16 = 4096
#define THRESH 0.01f
#define MAX_ROWS 8192

__device__ float g_partial[MAX_ROWS];
__device__ unsigned int g_counter = 0;

__global__ __launch_bounds__(BLOCK, 8)
void pulse_loss_kernel(const float* __restrict__ pred,
                       const float* __restrict__ lab,
                       float* __restrict__ out,
                       float scale, int total_rows) {
    __shared__ int s_qf, s_ql;
    __shared__ float s_sum[NWARP];
    __shared__ int s_is_last;

    const int t = threadIdx.x;
    const int wid = t >> 5;
    const int lid = t & 31;
    const long row = blockIdx.x;

    const float4* __restrict__ l4 = (const float4*)(lab  + row * H_HALF);
    const float4* __restrict__ p4 = (const float4*)(pred + row * H_HALF);

    if (t == 0) { s_qf = INT_MAX; s_ql = -1; }
    __syncthreads();   // init visible before any atomicMin/Max below

    // Pure streaming pass: unweighted sum of squares + quad-level mask extent.
    // Plain (default-cached) loads — experiment: __ldcs removed vs R15.
    float acc = 0.0f;
    int qmin = INT_MAX;
    int qmax = -1;
    #pragma unroll
    for (int i = 0; i < V4; i++) {
        const int v = t + i * BLOCK;          // quad index 0..1023
        const float4 l = l4[v];
        const float4 p = p4[v];
        const float d0 = p.x - l.x, d1 = p.y - l.y;
        const float d2 = p.z - l.z, d3 = p.w - l.w;
        acc += d0 * d0 + d1 * d1 + d2 * d2 + d3 * d3;
        const float m = fmaxf(fmaxf(fabsf(l.x), fabsf(l.y)),
                              fmaxf(fabsf(l.z), fabsf(l.w)));
        if (m > THRESH) { qmin = min(qmin, v); qmax = max(qmax, v); }
    }

    // Quad-level block reduce of first/last extents (order-independent atomics)
    const int wf = __reduce_min_sync(0xFFFFFFFFu, qmin);
    const int wl = __reduce_max_sync(0xFFFFFFFFu, qmax);
    if (lid == 0) {
        atomicMin(&s_qf, wf);
        atomicMax(&s_ql, wl);
    }
    __syncthreads();

    const int qf = s_qf;
    const int ql = s_ql;
    int first, last;
    if (qf == INT_MAX) {
        // all-insignificant row: argmax fallback -> no outside region
        first = 0;
        last  = H_HALF - 1;
    } else {
        // Element-precise refinement (uniform 16B loads, broadcast across block)
        const float4 lf = l4[qf];
        int fo = 3;
        if (fabsf(lf.z) > THRESH) fo = 2;
        if (fabsf(lf.y) > THRESH) fo = 1;
        if (fabsf(lf.x) > THRESH) fo = 0;
        first = qf * 4 + fo;

        const float4 llq = l4[ql];
        int lo = 0;
        if (fabsf(llq.y) > THRESH) lo = 1;
        if (fabsf(llq.z) > THRESH) lo = 2;
        if (fabsf(llq.w) > THRESH) lo = 3;
        last = ql * 4 + lo;
    }

    // Outside correction: elements in [0,first) and (last+1, H) get an EXTRA
    // 1x of d^2 (total weight 2). Typically 0-2 elements per row; reload from
    // global (L1/L2-hot). Fixed thread->index mapping: deterministic.
    {
        const float* __restrict__ lrow = lab  + row * H_HALF;
        const float* __restrict__ prow = pred + row * H_HALF;
        for (int e = t; e < first; e += BLOCK) {
            const float d = prow[e] - lrow[e];
            acc += d * d;
        }
        for (int e = last + 1 + t; e < H_HALF; e += BLOCK) {
            const float d = prow[e] - lrow[e];
            acc += d * d;
        }
    }

    // Block reduce sum (deterministic)
    #pragma unroll
    for (int o = 16; o > 0; o >>= 1)
        acc += __shfl_xor_sync(0xFFFFFFFFu, acc, o);
    if (lid == 0) s_sum[wid] = acc;
    __syncthreads();
    if (t == 0) {
        float v = 0.0f;
        #pragma unroll
        for (int w = 0; w < NWARP; w++) v += s_sum[w];
        g_partial[row] = v;
        __threadfence();
        unsigned int done = atomicAdd(&g_counter, 1u);
        s_is_last = (done == gridDim.x - 1) ? 1 : 0;
    }
    __syncthreads();

    // Last block: deterministic final reduction over all row partials
    if (s_is_last) {
        __threadfence();
        float facc = 0.0f;
        for (int i = t; i < total_rows; i += BLOCK)
            facc += __ldcg(&g_partial[i]);   // fixed order -> deterministic
        #pragma unroll
        for (int o = 16; o > 0; o >>= 1)
            facc += __shfl_xor_sync(0xFFFFFFFFu, facc, o);
        if (lid == 0) s_sum[wid] = facc;
        __syncthreads();
        if (t == 0) {
            float v = 0.0f;
            #pragma unroll
            for (int w = 0; w < NWARP; w++) v += s_sum[w];
            out[0] = v * scale;
            g_counter = 0;   // reset for next graph replay
        }
    }
}

extern "C" void kernel_launch(void* const* d_in, const int* in_sizes, int n_in,
                              void* d_out, int out_size) {
    const float* pred = (const float*)d_in[0];
    const float* lab  = (const float*)d_in[1];
    float* out = (float*)d_out;

    const long n = in_sizes[0];                 // total elements (B * N)
    const int total_rows = (int)(n / H_HALF);   // B * 2 half-rows
    const long B = total_rows / 2;
    const float scale = 1.0f / ((float)B * (float)H_HALF);

    pulse_loss_kernel<<<(unsigned)total_rows, BLOCK>>>(pred, lab, out, scale, total_rows);
}

// round 17
// speedup vs baseline: 1.0432x; 1.0432x over previous
#include <cuda_runtime.h>
#include <cuda_bf16.h>
#include <limits.h>

#define H_HALF 4096
#define BLOCK 256
#define NWARP (BLOCK / 32)
#define V4 4                 // 4 float4 per thread = 16 floats; 256*16 = 4096
#define THRESH 0.01f
#define MAX_ROWS 8192

__device__ float g_partial[MAX_ROWS];
__device__ unsigned int g_counter = 0;

__global__ __launch_bounds__(BLOCK)
void pulse_loss_kernel(const float* __restrict__ pred,
                       const float* __restrict__ lab,
                       float* __restrict__ out,
                       float scale, int total_rows) {
    __shared__ int s_first, s_last;
    __shared__ float s_sum[NWARP];
    __shared__ int s_is_last;

    const int t = threadIdx.x;
    const int wid = t >> 5;
    const int lid = t & 31;
    const long row = blockIdx.x;

    const float4* __restrict__ l4 = (const float4*)(lab  + row * H_HALF);
    const float4* __restrict__ p4 = (const float4*)(pred + row * H_HALF);

    if (t == 0) { s_first = INT_MAX; s_last = -1; }

    // Front-batch ALL loads (labels first: mask phase depends only on them;
    // pred loads stay in flight across the barrier).
    float4 l[V4];
    float4 p[V4];
    #pragma unroll
    for (int i = 0; i < V4; i++)
        l[i] = __ldcs(&l4[t + i * BLOCK]);
    #pragma unroll
    for (int i = 0; i < V4; i++)
        p[i] = __ldcs(&p4[t + i * BLOCK]);

    __syncthreads();   // s_first/s_last init visible before atomics below

    // Element-level first/last from labels
    int firstI = INT_MAX;
    int lastI  = -1;
    #pragma unroll
    for (int i = 0; i < V4; i++) {
        const int gi = (t + i * BLOCK) * 4;
        if (fabsf(l[i].x) > THRESH) { firstI = min(firstI, gi + 0); lastI = max(lastI, gi + 0); }
        if (fabsf(l[i].y) > THRESH) { firstI = min(firstI, gi + 1); lastI = max(lastI, gi + 1); }
        if (fabsf(l[i].z) > THRESH) { firstI = min(firstI, gi + 2); lastI = max(lastI, gi + 2); }
        if (fabsf(l[i].w) > THRESH) { firstI = min(firstI, gi + 3); lastI = max(lastI, gi + 3); }
    }
    const int wf = __reduce_min_sync(0xFFFFFFFFu, firstI);
    const int wl = __reduce_max_sync(0xFFFFFFFFu, lastI);
    if (lid == 0) {
        atomicMin(&s_first, wf);   // order-independent -> deterministic
        atomicMax(&s_last, wl);
    }
    __syncthreads();               // single barrier for the whole mask phase

    int first = s_first;
    int last  = s_last;
    if (first == INT_MAX) { first = 0; last = H_HALF - 1; }   // all-insignificant fallback

    // Weighted squared diffs (register-resident operands)
    float acc = 0.0f;
    #pragma unroll
    for (int i = 0; i < V4; i++) {
        const int gi = (t + i * BLOCK) * 4;
        const float d0 = p[i].x - l[i].x;
        const float d1 = p[i].y - l[i].y;
        const float d2 = p[i].z - l[i].z;
        const float d3 = p[i].w - l[i].w;
        const float w0 = (gi + 0 < first || gi + 0 > last) ? 2.0f : 1.0f;
        const float w1 = (gi + 1 < first || gi + 1 > last) ? 2.0f : 1.0f;
        const float w2 = (gi + 2 < first || gi + 2 > last) ? 2.0f : 1.0f;
        const float w3 = (gi + 3 < first || gi + 3 > last) ? 2.0f : 1.0f;
        acc += w0 * d0 * d0 + w1 * d1 * d1 + w2 * d2 * d2 + w3 * d3 * d3;
    }

    // Block reduce sum (deterministic)
    #pragma unroll
    for (int o = 16; o > 0; o >>= 1)
        acc += __shfl_xor_sync(0xFFFFFFFFu, acc, o);
    if (lid == 0) s_sum[wid] = acc;
    __syncthreads();
    if (t == 0) {
        float v = 0.0f;
        #pragma unroll
        for (int w = 0; w < NWARP; w++) v += s_sum[w];
        g_partial[row] = v;
        __threadfence();
        unsigned int done = atomicAdd(&g_counter, 1u);
        s_is_last = (done == gridDim.x - 1) ? 1 : 0;
    }
    __syncthreads();

    // Last block: deterministic final reduction over all row partials
    if (s_is_last) {
        __threadfence();
        float facc = 0.0f;
        for (int i = t; i < total_rows; i += BLOCK)
            facc += __ldcg(&g_partial[i]);   // fixed order -> deterministic
        #pragma unroll
        for (int o = 16; o > 0; o >>= 1)
            facc += __shfl_xor_sync(0xFFFFFFFFu, facc, o);
        if (lid == 0) s_sum[wid] = facc;
        __syncthreads();
        if (t == 0) {
            float v = 0.0f;
            #pragma unroll
            for (int w = 0; w < NWARP; w++) v += s_sum[w];
            out[0] = v * scale;
            g_counter = 0;   // reset for next graph replay
        }
    }
}

extern "C" void kernel_launch(void* const* d_in, const int* in_sizes, int n_in,
                              void* d_out, int out_size) {
    const float* pred = (const float*)d_in[0];
    const float* lab  = (const float*)d_in[1];
    float* out = (float*)d_out;

    const long n = in_sizes[0];                 // total elements (B * N)
    const int total_rows = (int)(n / H_HALF);   // B * 2 half-rows
    const long B = total_rows / 2;
    const float scale = 1.0f / ((float)B * (float)H_HALF);

    pulse_loss_kernel<<<(unsigned)total_rows, BLOCK>>>(pred, lab, out, scale, total_rows);
}